// round 2
// baseline (speedup 1.0000x reference)
#include <cuda_runtime.h>

// InvConditionalLinear forward: per-pixel 32x32 solve W z = x + sum log|det W|.
// B=16, C=32, H=W=48. One warp per pixel matrix, lane = row, registers packed
// as 16x f32x2. Unpivoted Gauss-Jordan (W = I + 0.1*N well conditioned).
// Pivot-row broadcast via smem (STS.128/LDS.128 broadcast) instead of SHFL;
// packed fma.rn.f32x2 updates; triangular trim at float4 granularity.

#define FULL_MASK 0xffffffffu

static constexpr int B = 16, C = 32, HW = 48 * 48;   // HW = 2304
static constexpr int PIX_PER_BLK = 8;                // 2304 % 8 == 0
static constexpr int MAT_STRIDE = 1057;              // 33*32 + 1
static constexpr int ROW_STRIDE = 33;

static __device__ float g_pixlogdet[B * HW];

__device__ __forceinline__ unsigned long long pack2(float x, float y) {
    unsigned long long r;
    asm("mov.b64 %0, {%1, %2};" : "=l"(r) : "r"(__float_as_uint(x)), "r"(__float_as_uint(y)));
    return r;
}
__device__ __forceinline__ float lo32(unsigned long long v) { return __uint_as_float((unsigned)v); }
__device__ __forceinline__ float hi32(unsigned long long v) { return __uint_as_float((unsigned)(v >> 32)); }
__device__ __forceinline__ unsigned long long ffma2(unsigned long long a, unsigned long long b,
                                                    unsigned long long c) {
    unsigned long long d;
    asm("fma.rn.f32x2 %0, %1, %2, %3;" : "=l"(d) : "l"(a), "l"(b), "l"(c));
    return d;
}

__global__ __launch_bounds__(256) void gj_solve_kernel(
    const float* __restrict__ input,   // [B, C, H, W]
    const float* __restrict__ weight,  // [B, C*C, H, W]
    float* __restrict__ out)           // z region of d_out
{
    __shared__ float s_w[PIX_PER_BLK * MAT_STRIDE];
    __shared__ float s_x[PIX_PER_BLK * ROW_STRIDE];
    __shared__ float s_z[PIX_PER_BLK * ROW_STRIDE];
    __shared__ __align__(16) float s_row[PIX_PER_BLK * 64];  // 2 buffers x 32 floats per warp

    const int t    = threadIdx.x;
    const int lane = t & 31;
    const int p    = t >> 5;
    const int q0   = blockIdx.x * PIX_PER_BLK;
    const int b    = q0 / HW;
    const int qm0  = q0 - b * HW;

    // ---- Phase 1: coalesced load of 8 matrices + rhs (vectorized over pixel axis) ----
    const float* wbase = weight + (size_t)b * (size_t)(C * C) * HW + qm0;
    #pragma unroll
    for (int it = 0; it < 8; ++it) {
        int idx = it * 256 + t;
        int c   = idx >> 1;                  // channel 0..1023 (row = c>>5, col = c&31)
        int pp  = (idx & 1) << 2;            // pixel 0 or 4
        float4 v = *reinterpret_cast<const float4*>(wbase + (size_t)c * HW + pp);
        int sb = (c >> 5) * ROW_STRIDE + (c & 31);
        s_w[(pp + 0) * MAT_STRIDE + sb] = v.x;
        s_w[(pp + 1) * MAT_STRIDE + sb] = v.y;
        s_w[(pp + 2) * MAT_STRIDE + sb] = v.z;
        s_w[(pp + 3) * MAT_STRIDE + sb] = v.w;
    }
    {
        int c = t >> 3, pp = t & 7;
        s_x[pp * ROW_STRIDE + c] =
            input[(size_t)b * C * HW + (size_t)c * HW + qm0 + pp];
    }
    __syncthreads();

    // ---- Phase 2: register-resident Gauss-Jordan (packed f32x2), lane = row ----
    unsigned long long a2[16];
    {
        const float* mr = s_w + p * MAT_STRIDE + lane * ROW_STRIDE;
        #pragma unroll
        for (int i = 0; i < 16; ++i) a2[i] = pack2(mr[2 * i], mr[2 * i + 1]);
    }
    float rhs = s_x[p * ROW_STRIDE + lane];

    float mypinv = 1.0f, mypiv = 1.0f;
    float* rwarp = s_row + p * 64;

    #pragma unroll
    for (int k = 0; k < 32; ++k) {
        const int kb = k >> 2;                  // first float4 block still needed
        float* rb = rwarp + ((k & 1) << 5);     // double buffer

        if (lane == k) {                        // pivot lane publishes its row
            #pragma unroll
            for (int q = kb; q < 8; ++q) {
                ulonglong2 v;
                v.x = a2[2 * q]; v.y = a2[2 * q + 1];
                *reinterpret_cast<ulonglong2*>(rb + 4 * q) = v;
            }
        }
        __syncwarp();

        unsigned long long pr[16];
        #pragma unroll
        for (int q = kb; q < 8; ++q) {
            ulonglong2 v = *reinterpret_cast<const ulonglong2*>(rb + 4 * q);
            pr[2 * q] = v.x; pr[2 * q + 1] = v.y;
        }

        const float piv  = (k & 1) ? hi32(pr[k >> 1]) : lo32(pr[k >> 1]);
        const float pinv = __fdividef(1.0f, piv);
        const float ak   = (k & 1) ? hi32(a2[k >> 1]) : lo32(a2[k >> 1]);
        const float m    = (lane == k) ? 0.0f : ak * pinv;
        if (lane == k) { mypiv = piv; mypinv = pinv; }

        const unsigned long long nm2 = pack2(-m, -m);
        #pragma unroll
        for (int i = 2 * kb; i < 16; ++i)
            a2[i] = ffma2(nm2, pr[i], a2[i]);

        const float prhs = __shfl_sync(FULL_MASK, rhs, k);
        rhs = fmaf(-m, prhs, rhs);
    }

    const float z = rhs * mypinv;

    // per-matrix log|det| = sum of log|pivot| over lanes
    float s = __logf(fabsf(mypiv));
    #pragma unroll
    for (int off = 16; off; off >>= 1) s += __shfl_xor_sync(FULL_MASK, s, off);
    if (lane == 0) g_pixlogdet[q0 + p] = s;

    s_z[p * ROW_STRIDE + lane] = z;
    __syncthreads();

    // ---- Phase 3: coalesced store of z ----
    {
        int c = t >> 3, pp = t & 7;
        out[(size_t)b * C * HW + (size_t)c * HW + qm0 + pp] = s_z[pp * ROW_STRIDE + c];
    }
}

// Deterministic fixed-order per-batch reduction of 2304 pixel logdets.
__global__ __launch_bounds__(256) void logdet_reduce_kernel(
    const float* __restrict__ logdet_in, float* __restrict__ out)
{
    __shared__ float sm[256];
    const int b = blockIdx.x, t = threadIdx.x;
    float s = 0.0f;
    #pragma unroll
    for (int r = 0; r < 9; ++r)                 // 2304 = 9 * 256
        s += g_pixlogdet[b * HW + r * 256 + t];
    sm[t] = s;
    __syncthreads();
    #pragma unroll
    for (int off = 128; off; off >>= 1) {
        if (t < off) sm[t] += sm[t + off];
        __syncthreads();
    }
    if (t == 0) out[(size_t)B * C * HW + b] = logdet_in[b] - sm[0];
}

extern "C" void kernel_launch(void* const* d_in, const int* in_sizes, int n_in,
                              void* d_out, int out_size)
{
    const float* input  = (const float*)d_in[0];
    const float* weight = (const float*)d_in[1];
    const float* logdet = (const float*)d_in[2];
    float* out = (float*)d_out;

    gj_solve_kernel<<<(B * HW) / PIX_PER_BLK, 256>>>(input, weight, out);
    logdet_reduce_kernel<<<B, 256>>>(logdet, out);
}

// round 3
// speedup vs baseline: 1.3129x; 1.3129x over previous
#include <cuda_runtime.h>

// InvConditionalLinear forward: per-pixel 32x32 solve W z = x, sum log|det W|.
// B=16, C=32, H=W=48 (HW=2304). 16 lanes per matrix (2 matrices per warp),
// each lane owns 2 rows as f32x2. Width-16 shfl broadcasts serve both matrices
// with one instruction. Unpivoted Gauss-Jordan (W = I + 0.1*N well conditioned).

#define FULL_MASK 0xffffffffu

static constexpr int B = 16, C = 32, HW = 48 * 48;     // 2304
static constexpr int PIX = 8;                          // pixels per block (128 thr)
static constexpr int RSTR = 36;                        // row stride (floats)
static constexpr int MSTR = 32 * RSTR;                 // 1152 floats per pixel
static constexpr int BLOCKS_PER_BATCH = HW / PIX;      // 288

static __device__ float g_pixlogdet[B * HW];
static __device__ int   g_done[B];                     // zero-init; reset by finisher

__device__ __forceinline__ unsigned long long pack2(float x, float y) {
    unsigned long long r;
    asm("mov.b64 %0, {%1, %2};" : "=l"(r) : "r"(__float_as_uint(x)), "r"(__float_as_uint(y)));
    return r;
}
__device__ __forceinline__ float lo32(unsigned long long v) { return __uint_as_float((unsigned)v); }
__device__ __forceinline__ float hi32(unsigned long long v) { return __uint_as_float((unsigned)(v >> 32)); }
__device__ __forceinline__ unsigned long long ffma2(unsigned long long a, unsigned long long b,
                                                    unsigned long long c) {
    unsigned long long d;
    asm("fma.rn.f32x2 %0, %1, %2, %3;" : "=l"(d) : "l"(a), "l"(b), "l"(c));
    return d;
}

__global__ __launch_bounds__(128) void gj_solve_kernel(
    const float* __restrict__ input,     // [B, C, H, W]
    const float* __restrict__ weight,    // [B, C*C, H, W]
    const float* __restrict__ logdet_in, // [B]
    float* __restrict__ out)             // z [B,C,H,W] then logdet [B]
{
    __shared__ float s_w[PIX * MSTR];    // 36 KB
    __shared__ float s_x[PIX * 32];
    __shared__ float s_z[PIX * 32];
    __shared__ float s_red[128];
    __shared__ int   s_last;

    const int t    = threadIdx.x;
    const int lane = t & 31;
    const int w    = t >> 5;
    const int q0   = blockIdx.x * PIX;
    const int b    = q0 / HW;
    const int qm0  = q0 - b * HW;

    // ---- Phase 1: coalesced global load, stage to smem ----
    const float* wbase = weight + (size_t)b * (size_t)(C * C) * HW + qm0;
    #pragma unroll
    for (int it = 0; it < 16; ++it) {
        int idx = it * 128 + t;                  // 0..2047
        int c   = idx >> 1;                      // channel 0..1023
        int pp  = (idx & 1) << 2;                // pixel 0 or 4
        float4 v = *reinterpret_cast<const float4*>(wbase + (size_t)c * HW + pp);
        int sb = (c >> 5) * RSTR + (c & 31);     // row = c>>5, col = c&31
        s_w[(pp + 0) * MSTR + sb] = v.x;
        s_w[(pp + 1) * MSTR + sb] = v.y;
        s_w[(pp + 2) * MSTR + sb] = v.z;
        s_w[(pp + 3) * MSTR + sb] = v.w;
    }
    #pragma unroll
    for (int it = 0; it < 2; ++it) {
        int c = it * 16 + (t >> 3), pp = t & 7;
        s_x[pp * 32 + c] = input[(size_t)b * C * HW + (size_t)c * HW + qm0 + pp];
    }
    __syncthreads();

    // ---- Phase 2: Gauss-Jordan, 16 lanes per matrix, lane owns rows hl, hl+16 ----
    const int hl  = lane & 15;
    const int pix = 2 * w + (lane >> 4);

    unsigned long long a2[16], b2[16];
    {
        const float* rA = s_w + pix * MSTR + hl * RSTR;
        const float* rB = s_w + pix * MSTR + (hl + 16) * RSTR;
        #pragma unroll
        for (int q = 0; q < 8; ++q) {
            float4 va = *reinterpret_cast<const float4*>(rA + 4 * q);
            float4 vb = *reinterpret_cast<const float4*>(rB + 4 * q);
            a2[2 * q] = pack2(va.x, va.y); a2[2 * q + 1] = pack2(va.z, va.w);
            b2[2 * q] = pack2(vb.x, vb.y); b2[2 * q + 1] = pack2(vb.z, vb.w);
        }
    }
    float rhsA = s_x[pix * 32 + hl];
    float rhsB = s_x[pix * 32 + hl + 16];

    float pivA = 1.0f, pivB = 1.0f, piA = 1.0f, piB = 1.0f;

    #pragma unroll
    for (int k = 0; k < 32; ++k) {
        const int kb2 = (k >> 2) * 2;     // first live f32x2 block (col >= 4*(k/4))
        const int own = k & 15;           // owner lane within half
        const int ip  = k >> 1;           // f32x2 block holding the pivot element

        // broadcast pivot block first (serves both matrices)
        unsigned long long pb =
            __shfl_sync(FULL_MASK, (k < 16) ? a2[ip] : b2[ip], own, 16);
        const float piv  = (k & 1) ? hi32(pb) : lo32(pb);
        const float pinv = __fdividef(1.0f, piv);

        const float eA = (k & 1) ? hi32(a2[ip]) : lo32(a2[ip]);
        const float eB = (k & 1) ? hi32(b2[ip]) : lo32(b2[ip]);
        const float mA = ((k < 16) && hl == own) ? 0.0f : eA * pinv;
        const float mB = ((k >= 16) && hl == own) ? 0.0f : eB * pinv;
        if (k < 16) { if (hl == own) { pivA = piv; piA = pinv; } }
        else        { if (hl == own) { pivB = piv; piB = pinv; } }

        const unsigned long long nmA = pack2(-mA, -mA);
        const unsigned long long nmB = pack2(-mB, -mB);

        #pragma unroll
        for (int i = kb2; i < 16; ++i) {
            unsigned long long pr = (i == ip)
                ? pb
                : __shfl_sync(FULL_MASK, (k < 16) ? a2[i] : b2[i], own, 16);
            a2[i] = ffma2(nmA, pr, a2[i]);
            b2[i] = ffma2(nmB, pr, b2[i]);
        }

        const float rk = __shfl_sync(FULL_MASK, (k < 16) ? rhsA : rhsB, own, 16);
        rhsA = fmaf(-mA, rk, rhsA);
        rhsB = fmaf(-mB, rk, rhsB);
    }

    const float zA = rhsA * piA;
    const float zB = rhsB * piB;

    // per-matrix log|det| = sum over 16 lanes of log|pivots owned| (2 each)
    float s = __logf(fabsf(pivA)) + __logf(fabsf(pivB));
    #pragma unroll
    for (int off = 8; off; off >>= 1) s += __shfl_xor_sync(FULL_MASK, s, off, 16);
    if (hl == 0) g_pixlogdet[q0 + pix] = s;

    s_z[pix * 32 + hl]      = zA;
    s_z[pix * 32 + hl + 16] = zB;
    __syncthreads();

    // ---- Phase 3: coalesced store of z ----
    #pragma unroll
    for (int it = 0; it < 2; ++it) {
        int c = it * 16 + (t >> 3), pp = t & 7;
        out[(size_t)b * C * HW + (size_t)c * HW + qm0 + pp] = s_z[pp * 32 + c];
    }

    // ---- Phase 4: last block per batch reduces the 2304 pixel logdets ----
    __threadfence();
    if (t == 0) {
        int v = atomicAdd(&g_done[b], 1);
        s_last = (v == BLOCKS_PER_BATCH - 1);
    }
    __syncthreads();
    if (s_last) {
        __threadfence();
        float acc = 0.0f;
        #pragma unroll
        for (int r = 0; r < 18; ++r)                 // 2304 = 18 * 128, fixed order
            acc += g_pixlogdet[b * HW + r * 128 + t];
        s_red[t] = acc;
        __syncthreads();
        #pragma unroll
        for (int off = 64; off; off >>= 1) {
            if (t < off) s_red[t] += s_red[t + off];
            __syncthreads();
        }
        if (t == 0) {
            out[(size_t)B * C * HW + b] = logdet_in[b] - s_red[0];
            g_done[b] = 0;                           // reset for next graph replay
        }
    }
}

extern "C" void kernel_launch(void* const* d_in, const int* in_sizes, int n_in,
                              void* d_out, int out_size)
{
    const float* input  = (const float*)d_in[0];
    const float* weight = (const float*)d_in[1];
    const float* logdet = (const float*)d_in[2];
    float* out = (float*)d_out;

    gj_solve_kernel<<<(B * HW) / PIX, 128>>>(input, weight, logdet, out);
}